// round 4
// baseline (speedup 1.0000x reference)
#include <cuda_runtime.h>
#include <cuda_bf16.h>
#include <math_constants.h>

// MASS_18897856102446: fused weighted-sq-dist attention
// out[b,n] = out_dist[b,n] * softmax_n(-(att_dist[b,n]*mask[b,n]))
// B=1024, N=200, E=128 (fp32). HBM-bound: m + m_c = ~210MB streamed once.
// R4: algebraic expansion (sq-dist -> Cq + sum m(v*m - 2u), shared u/v/Cq for
//     both tensors) halves FMA work; dual-lane butterfly (6 shuffles for both
//     reductions); __ldcs streaming loads.

constexpr int N_ = 200;
constexpr int E_ = 128;
constexpr int NWARP = 8;
constexpr int NTHR = NWARP * 32;

__global__ __launch_bounds__(NTHR)
void mass_kernel(const float* __restrict__ q,
                 const float* __restrict__ q_p,
                 const float* __restrict__ m,
                 const float* __restrict__ m_c,
                 const float* __restrict__ A1,
                 const float* __restrict__ A2,
                 const float* __restrict__ biases,
                 const float* __restrict__ mask,
                 float* __restrict__ out)
{
    const int b    = blockIdx.x;
    const int tid  = threadIdx.x;
    const int warp = tid >> 5;
    const int lane = tid & 31;

    __shared__ float4 s_v[E_ / 4], s_m2u[E_ / 4];
    __shared__ float  s_cq[4];
    __shared__ float  s_logit[N_], s_outd[N_];
    __shared__ float  s_red[NWARP];

    // Stage v = a1^2 + a2^2, m2u = -2*(a1^2 q + a2^2 qp); reduce Cq.
    if (tid < E_) {
        const float a1 = A1[tid];
        const float a2 = A2[tid];
        const float a1s = a1 * a1, a2s = a2 * a2;
        const float qv  = q  [(size_t)b * E_ + tid];
        const float qpv = q_p[(size_t)b * E_ + tid];
        reinterpret_cast<float*>(s_v)  [tid] = a1s + a2s;
        reinterpret_cast<float*>(s_m2u)[tid] = -2.f * (a1s * qv + a2s * qpv);
        float c = a1s * qv * qv + a2s * qpv * qpv;
        #pragma unroll
        for (int o = 16; o; o >>= 1)
            c += __shfl_xor_sync(0xffffffffu, c, o);
        if (lane == 0) s_cq[warp] = c;   // warps 0..3
    }
    __syncthreads();

    const float4 vv = s_v[lane];
    const float4 mu = s_m2u[lane];
    const float  Cq = s_cq[0] + s_cq[1] + s_cq[2] + s_cq[3];

    const float4* __restrict__ m4 = reinterpret_cast<const float4*>(m   + (size_t)b * N_ * E_);
    const float4* __restrict__ c4 = reinterpret_cast<const float4*>(m_c + (size_t)b * N_ * E_);
    const float*  __restrict__ bia = biases + (size_t)b * N_;
    const float*  __restrict__ msk = mask   + (size_t)b * N_;

    // sa = sum_e m*(v*m - 2u); so likewise with m_c. 16 FFMA per row.
    auto body = [&](const float4 mv, const float4 cv, float& sa, float& so) {
        float t;
        t = fmaf(vv.x, mv.x, mu.x); sa = mv.x * t;
        t = fmaf(vv.y, mv.y, mu.y); sa = fmaf(mv.y, t, sa);
        t = fmaf(vv.z, mv.z, mu.z); sa = fmaf(mv.z, t, sa);
        t = fmaf(vv.w, mv.w, mu.w); sa = fmaf(mv.w, t, sa);
        t = fmaf(vv.x, cv.x, mu.x); so = cv.x * t;
        t = fmaf(vv.y, cv.y, mu.y); so = fmaf(cv.y, t, so);
        t = fmaf(vv.z, cv.z, mu.z); so = fmaf(cv.z, t, so);
        t = fmaf(vv.w, cv.w, mu.w); so = fmaf(cv.w, t, so);
    };

    // Dual reduction: sa -> lanes<16, so -> lanes>=16; 6 shuffles total.
    auto finish = [&](int n, float sa, float so) {
        const float osa = __shfl_xor_sync(0xffffffffu, sa, 16);
        const float oso = __shfl_xor_sync(0xffffffffu, so, 16);
        float val = (lane < 16) ? (sa + osa) : (so + oso);
        #pragma unroll
        for (int o = 8; o; o >>= 1)
            val += __shfl_xor_sync(0xffffffffu, val, o);
        if (lane == 0) {
            const float add = Cq + 2.f * bia[n];
            s_logit[n] = -((val + add) * msk[n]);
        } else if (lane == 16) {
            const float add = Cq + 2.f * bia[n];
            s_outd[n] = (val + add) * msk[n];
        }
    };

    // 25 rows per warp. Unroll 8 rows: 16 independent streaming float4 loads.
    #pragma unroll 1
    for (int k = 0; k < 24; k += 8) {
        const int n0 = warp + (k + 0) * NWARP;
        const int n1 = warp + (k + 1) * NWARP;
        const int n2 = warp + (k + 2) * NWARP;
        const int n3 = warp + (k + 3) * NWARP;
        const int n4 = warp + (k + 4) * NWARP;
        const int n5 = warp + (k + 5) * NWARP;
        const int n6 = warp + (k + 6) * NWARP;
        const int n7 = warp + (k + 7) * NWARP;

        const float4 mv0 = __ldcs(&m4[n0 * (E_ / 4) + lane]);
        const float4 mv1 = __ldcs(&m4[n1 * (E_ / 4) + lane]);
        const float4 mv2 = __ldcs(&m4[n2 * (E_ / 4) + lane]);
        const float4 mv3 = __ldcs(&m4[n3 * (E_ / 4) + lane]);
        const float4 mv4 = __ldcs(&m4[n4 * (E_ / 4) + lane]);
        const float4 mv5 = __ldcs(&m4[n5 * (E_ / 4) + lane]);
        const float4 mv6 = __ldcs(&m4[n6 * (E_ / 4) + lane]);
        const float4 mv7 = __ldcs(&m4[n7 * (E_ / 4) + lane]);
        const float4 cv0 = __ldcs(&c4[n0 * (E_ / 4) + lane]);
        const float4 cv1 = __ldcs(&c4[n1 * (E_ / 4) + lane]);
        const float4 cv2 = __ldcs(&c4[n2 * (E_ / 4) + lane]);
        const float4 cv3 = __ldcs(&c4[n3 * (E_ / 4) + lane]);
        const float4 cv4 = __ldcs(&c4[n4 * (E_ / 4) + lane]);
        const float4 cv5 = __ldcs(&c4[n5 * (E_ / 4) + lane]);
        const float4 cv6 = __ldcs(&c4[n6 * (E_ / 4) + lane]);
        const float4 cv7 = __ldcs(&c4[n7 * (E_ / 4) + lane]);

        float sa0, so0, sa1, so1, sa2, so2, sa3, so3;
        float sa4, so4, sa5, so5, sa6, so6, sa7, so7;
        body(mv0, cv0, sa0, so0);
        body(mv1, cv1, sa1, so1);
        body(mv2, cv2, sa2, so2);
        body(mv3, cv3, sa3, so3);
        body(mv4, cv4, sa4, so4);
        body(mv5, cv5, sa5, so5);
        body(mv6, cv6, sa6, so6);
        body(mv7, cv7, sa7, so7);

        finish(n0, sa0, so0);
        finish(n1, sa1, so1);
        finish(n2, sa2, so2);
        finish(n3, sa3, so3);
        finish(n4, sa4, so4);
        finish(n5, sa5, so5);
        finish(n6, sa6, so6);
        finish(n7, sa7, so7);
    }
    // Tail row: n = warp + 192
    {
        const int n = warp + 24 * NWARP;
        const float4 mv = __ldcs(&m4[n * (E_ / 4) + lane]);
        const float4 cv = __ldcs(&c4[n * (E_ / 4) + lane]);
        float sa, so;
        body(mv, cv, sa, so);
        finish(n, sa, so);
    }
    __syncthreads();

    // Block softmax over N_=200.
    const float v = (tid < N_) ? s_logit[tid] : -CUDART_INF_F;

    float wm = v;
    #pragma unroll
    for (int o = 16; o; o >>= 1)
        wm = fmaxf(wm, __shfl_xor_sync(0xffffffffu, wm, o));
    if (lane == 0) s_red[warp] = wm;
    __syncthreads();

    float mx = s_red[0];
    #pragma unroll
    for (int i = 1; i < NWARP; i++) mx = fmaxf(mx, s_red[i]);

    const float ex = (tid < N_) ? __expf(v - mx) : 0.f;

    float ws = ex;
    #pragma unroll
    for (int o = 16; o; o >>= 1)
        ws += __shfl_xor_sync(0xffffffffu, ws, o);
    __syncthreads();
    if (lane == 0) s_red[warp] = ws;
    __syncthreads();

    float tot = s_red[0];
    #pragma unroll
    for (int i = 1; i < NWARP; i++) tot += s_red[i];
    const float inv = 1.f / tot;

    if (tid < N_)
        out[(size_t)b * N_ + tid] = s_outd[tid] * ex * inv;
}

extern "C" void kernel_launch(void* const* d_in, const int* in_sizes, int n_in,
                              void* d_out, int out_size)
{
    const float* q      = (const float*)d_in[0];
    const float* q_p    = (const float*)d_in[1];
    const float* m      = (const float*)d_in[2];
    const float* m_c    = (const float*)d_in[3];
    const float* A1     = (const float*)d_in[4];
    const float* A2     = (const float*)d_in[5];
    const float* biases = (const float*)d_in[6];
    const float* mask   = (const float*)d_in[7];
    float* out = (float*)d_out;

    const int B = in_sizes[0] / E_;   // 1024
    mass_kernel<<<B, NTHR>>>(q, q_p, m, m_c, A1, A2, biases, mask, out);
}

// round 5
// speedup vs baseline: 1.7116x; 1.7116x over previous
#include <cuda_runtime.h>
#include <cuda_bf16.h>
#include <math_constants.h>

// MASS_18897856102446: fused weighted-sq-dist attention
// out[b,n] = out_dist[b,n] * softmax_n(-(att_dist[b,n]*mask[b,n]))
// B=1024, N=200, E=128 (fp32). HBM-bound: m + m_c = ~210MB streamed once.
// R5: R3 load structure (plain float4, 8-row unroll, 16 loads in flight)
//     + R4 algebraic expansion (16 FFMA/row). No __ldcs. Reg cap via
//     __launch_bounds__ to keep 4+ CTAs/SM.

constexpr int N_ = 200;
constexpr int E_ = 128;
constexpr int NWARP = 8;
constexpr int NTHR = NWARP * 32;

__global__ __launch_bounds__(NTHR, 5)
void mass_kernel(const float* __restrict__ q,
                 const float* __restrict__ q_p,
                 const float* __restrict__ m,
                 const float* __restrict__ m_c,
                 const float* __restrict__ A1,
                 const float* __restrict__ A2,
                 const float* __restrict__ biases,
                 const float* __restrict__ mask,
                 float* __restrict__ out)
{
    const int b    = blockIdx.x;
    const int tid  = threadIdx.x;
    const int warp = tid >> 5;
    const int lane = tid & 31;

    __shared__ float4 s_v[E_ / 4], s_m2u[E_ / 4];
    __shared__ float  s_cq[4];
    __shared__ float  s_logit[N_], s_outd[N_];
    __shared__ float  s_red[NWARP];

    // Stage v = a1^2 + a2^2, m2u = -2*(a1^2 q + a2^2 qp); reduce Cq.
    if (tid < E_) {
        const float a1 = A1[tid];
        const float a2 = A2[tid];
        const float a1s = a1 * a1, a2s = a2 * a2;
        const float qv  = q  [(size_t)b * E_ + tid];
        const float qpv = q_p[(size_t)b * E_ + tid];
        reinterpret_cast<float*>(s_v)  [tid] = a1s + a2s;
        reinterpret_cast<float*>(s_m2u)[tid] = -2.f * (a1s * qv + a2s * qpv);
        float c = a1s * qv * qv + a2s * qpv * qpv;
        #pragma unroll
        for (int o = 16; o; o >>= 1)
            c += __shfl_xor_sync(0xffffffffu, c, o);
        if (lane == 0) s_cq[warp] = c;   // warps 0..3
    }
    __syncthreads();

    const float4 vv = s_v[lane];
    const float4 mu = s_m2u[lane];
    const float  Cq = s_cq[0] + s_cq[1] + s_cq[2] + s_cq[3];

    const float4* __restrict__ m4 = reinterpret_cast<const float4*>(m   + (size_t)b * N_ * E_);
    const float4* __restrict__ c4 = reinterpret_cast<const float4*>(m_c + (size_t)b * N_ * E_);
    const float*  __restrict__ bia = biases + (size_t)b * N_;
    const float*  __restrict__ msk = mask   + (size_t)b * N_;

    // sa = sum_e m*(v*m - 2u); so likewise with m_c. 16 FFMA per row.
    auto body = [&](const float4 mv, const float4 cv, float& sa, float& so) {
        float t;
        t = fmaf(vv.x, mv.x, mu.x); sa = mv.x * t;
        t = fmaf(vv.y, mv.y, mu.y); sa = fmaf(mv.y, t, sa);
        t = fmaf(vv.z, mv.z, mu.z); sa = fmaf(mv.z, t, sa);
        t = fmaf(vv.w, mv.w, mu.w); sa = fmaf(mv.w, t, sa);
        t = fmaf(vv.x, cv.x, mu.x); so = cv.x * t;
        t = fmaf(vv.y, cv.y, mu.y); so = fmaf(cv.y, t, so);
        t = fmaf(vv.z, cv.z, mu.z); so = fmaf(cv.z, t, so);
        t = fmaf(vv.w, cv.w, mu.w); so = fmaf(cv.w, t, so);
    };

    auto finish = [&](int n, float sa, float so) {
        #pragma unroll
        for (int o = 16; o; o >>= 1) {
            sa += __shfl_xor_sync(0xffffffffu, sa, o);
            so += __shfl_xor_sync(0xffffffffu, so, o);
        }
        if (lane == 0) {
            const float add = Cq + 2.f * bia[n];
            const float mk  = msk[n];
            s_logit[n] = -((sa + add) * mk);
            s_outd[n]  = (so + add) * mk;
        }
    };

    // 25 rows per warp. Unroll 8 rows: 16 independent float4 loads in flight.
    #pragma unroll 1
    for (int k = 0; k < 24; k += 8) {
        const int n0 = warp + (k + 0) * NWARP;
        const int n1 = warp + (k + 1) * NWARP;
        const int n2 = warp + (k + 2) * NWARP;
        const int n3 = warp + (k + 3) * NWARP;
        const int n4 = warp + (k + 4) * NWARP;
        const int n5 = warp + (k + 5) * NWARP;
        const int n6 = warp + (k + 6) * NWARP;
        const int n7 = warp + (k + 7) * NWARP;

        const float4 mv0 = m4[n0 * (E_ / 4) + lane];
        const float4 mv1 = m4[n1 * (E_ / 4) + lane];
        const float4 mv2 = m4[n2 * (E_ / 4) + lane];
        const float4 mv3 = m4[n3 * (E_ / 4) + lane];
        const float4 mv4 = m4[n4 * (E_ / 4) + lane];
        const float4 mv5 = m4[n5 * (E_ / 4) + lane];
        const float4 mv6 = m4[n6 * (E_ / 4) + lane];
        const float4 mv7 = m4[n7 * (E_ / 4) + lane];
        const float4 cv0 = c4[n0 * (E_ / 4) + lane];
        const float4 cv1 = c4[n1 * (E_ / 4) + lane];
        const float4 cv2 = c4[n2 * (E_ / 4) + lane];
        const float4 cv3 = c4[n3 * (E_ / 4) + lane];
        const float4 cv4 = c4[n4 * (E_ / 4) + lane];
        const float4 cv5 = c4[n5 * (E_ / 4) + lane];
        const float4 cv6 = c4[n6 * (E_ / 4) + lane];
        const float4 cv7 = c4[n7 * (E_ / 4) + lane];

        float sa0, so0, sa1, so1, sa2, so2, sa3, so3;
        float sa4, so4, sa5, so5, sa6, so6, sa7, so7;
        body(mv0, cv0, sa0, so0);
        body(mv1, cv1, sa1, so1);
        body(mv2, cv2, sa2, so2);
        body(mv3, cv3, sa3, so3);
        body(mv4, cv4, sa4, so4);
        body(mv5, cv5, sa5, so5);
        body(mv6, cv6, sa6, so6);
        body(mv7, cv7, sa7, so7);

        finish(n0, sa0, so0);
        finish(n1, sa1, so1);
        finish(n2, sa2, so2);
        finish(n3, sa3, so3);
        finish(n4, sa4, so4);
        finish(n5, sa5, so5);
        finish(n6, sa6, so6);
        finish(n7, sa7, so7);
    }
    // Tail row: n = warp + 192
    {
        const int n = warp + 24 * NWARP;
        const float4 mv = m4[n * (E_ / 4) + lane];
        const float4 cv = c4[n * (E_ / 4) + lane];
        float sa, so;
        body(mv, cv, sa, so);
        finish(n, sa, so);
    }
    __syncthreads();

    // Block softmax over N_=200.
    const float v = (tid < N_) ? s_logit[tid] : -CUDART_INF_F;

    float wm = v;
    #pragma unroll
    for (int o = 16; o; o >>= 1)
        wm = fmaxf(wm, __shfl_xor_sync(0xffffffffu, wm, o));
    if (lane == 0) s_red[warp] = wm;
    __syncthreads();

    float mx = s_red[0];
    #pragma unroll
    for (int i = 1; i < NWARP; i++) mx = fmaxf(mx, s_red[i]);

    const float ex = (tid < N_) ? __expf(v - mx) : 0.f;

    float ws = ex;
    #pragma unroll
    for (int o = 16; o; o >>= 1)
        ws += __shfl_xor_sync(0xffffffffu, ws, o);
    __syncthreads();
    if (lane == 0) s_red[warp] = ws;
    __syncthreads();

    float tot = s_red[0];
    #pragma unroll
    for (int i = 1; i < NWARP; i++) tot += s_red[i];
    const float inv = 1.f / tot;

    if (tid < N_)
        out[(size_t)b * N_ + tid] = s_outd[tid] * ex * inv;
}

extern "C" void kernel_launch(void* const* d_in, const int* in_sizes, int n_in,
                              void* d_out, int out_size)
{
    const float* q      = (const float*)d_in[0];
    const float* q_p    = (const float*)d_in[1];
    const float* m      = (const float*)d_in[2];
    const float* m_c    = (const float*)d_in[3];
    const float* A1     = (const float*)d_in[4];
    const float* A2     = (const float*)d_in[5];
    const float* biases = (const float*)d_in[6];
    const float* mask   = (const float*)d_in[7];
    float* out = (float*)d_out;

    const int B = in_sizes[0] / E_;   // 1024
    mass_kernel<<<B, NTHR>>>(q, q_p, m, m_c, A1, A2, biases, mask, out);
}

// round 6
// speedup vs baseline: 1.9897x; 1.1625x over previous
#include <cuda_runtime.h>
#include <cuda_bf16.h>
#include <math_constants.h>

// MASS_18897856102446: fused weighted-sq-dist attention
// out[b,n] = out_dist[b,n] * softmax_n(-(att_dist[b,n]*mask[b,n]))
// B=1024, N=200, E=128 (fp32). HBM-bound: m + m_c = ~210MB streamed once.
// R6: 128-thread CTAs (4 warps), grid=1024 -> 7 CTAs/SM, SINGLE WAVE
//     (was 2 waves with 42%-full tail at 256-thread CTAs). Same R5 body:
//     expanded-square 16-FFMA rows, 8-row unroll, 16 float4 in flight.

constexpr int N_ = 200;
constexpr int E_ = 128;
constexpr int NWARP = 4;
constexpr int NTHR = NWARP * 32;   // 128

__global__ __launch_bounds__(NTHR, 8)
void mass_kernel(const float* __restrict__ q,
                 const float* __restrict__ q_p,
                 const float* __restrict__ m,
                 const float* __restrict__ m_c,
                 const float* __restrict__ A1,
                 const float* __restrict__ A2,
                 const float* __restrict__ biases,
                 const float* __restrict__ mask,
                 float* __restrict__ out)
{
    const int b    = blockIdx.x;
    const int tid  = threadIdx.x;
    const int warp = tid >> 5;
    const int lane = tid & 31;

    __shared__ float4 s_v[E_ / 4], s_m2u[E_ / 4];
    __shared__ float  s_cq[NWARP];
    __shared__ float  s_logit[N_], s_outd[N_];
    __shared__ float  s_red[NWARP];

    // Stage v = a1^2 + a2^2, m2u = -2*(a1^2 q + a2^2 qp); reduce Cq.
    // Exactly 128 threads = E_.
    {
        const float a1 = A1[tid];
        const float a2 = A2[tid];
        const float a1s = a1 * a1, a2s = a2 * a2;
        const float qv  = q  [(size_t)b * E_ + tid];
        const float qpv = q_p[(size_t)b * E_ + tid];
        reinterpret_cast<float*>(s_v)  [tid] = a1s + a2s;
        reinterpret_cast<float*>(s_m2u)[tid] = -2.f * (a1s * qv + a2s * qpv);
        float c = a1s * qv * qv + a2s * qpv * qpv;
        #pragma unroll
        for (int o = 16; o; o >>= 1)
            c += __shfl_xor_sync(0xffffffffu, c, o);
        if (lane == 0) s_cq[warp] = c;
    }
    __syncthreads();

    const float4 vv = s_v[lane];
    const float4 mu = s_m2u[lane];
    const float  Cq = s_cq[0] + s_cq[1] + s_cq[2] + s_cq[3];

    const float4* __restrict__ m4 = reinterpret_cast<const float4*>(m   + (size_t)b * N_ * E_);
    const float4* __restrict__ c4 = reinterpret_cast<const float4*>(m_c + (size_t)b * N_ * E_);
    const float*  __restrict__ bia = biases + (size_t)b * N_;
    const float*  __restrict__ msk = mask   + (size_t)b * N_;

    // sa = sum_e m*(v*m - 2u); so likewise with m_c. 16 FFMA per row.
    auto body = [&](const float4 mv, const float4 cv, float& sa, float& so) {
        float t;
        t = fmaf(vv.x, mv.x, mu.x); sa = mv.x * t;
        t = fmaf(vv.y, mv.y, mu.y); sa = fmaf(mv.y, t, sa);
        t = fmaf(vv.z, mv.z, mu.z); sa = fmaf(mv.z, t, sa);
        t = fmaf(vv.w, mv.w, mu.w); sa = fmaf(mv.w, t, sa);
        t = fmaf(vv.x, cv.x, mu.x); so = cv.x * t;
        t = fmaf(vv.y, cv.y, mu.y); so = fmaf(cv.y, t, so);
        t = fmaf(vv.z, cv.z, mu.z); so = fmaf(cv.z, t, so);
        t = fmaf(vv.w, cv.w, mu.w); so = fmaf(cv.w, t, so);
    };

    auto finish = [&](int n, float sa, float so) {
        #pragma unroll
        for (int o = 16; o; o >>= 1) {
            sa += __shfl_xor_sync(0xffffffffu, sa, o);
            so += __shfl_xor_sync(0xffffffffu, so, o);
        }
        if (lane == 0) {
            const float add = Cq + 2.f * bia[n];
            const float mk  = msk[n];
            s_logit[n] = -((sa + add) * mk);
            s_outd[n]  = (so + add) * mk;
        }
    };

    // 50 rows per warp (stride NWARP=4). 6 groups of 8 rows, then 2 tail rows.
    #pragma unroll 1
    for (int k = 0; k < 48; k += 8) {
        const int n0 = warp + (k + 0) * NWARP;
        const int n1 = warp + (k + 1) * NWARP;
        const int n2 = warp + (k + 2) * NWARP;
        const int n3 = warp + (k + 3) * NWARP;
        const int n4 = warp + (k + 4) * NWARP;
        const int n5 = warp + (k + 5) * NWARP;
        const int n6 = warp + (k + 6) * NWARP;
        const int n7 = warp + (k + 7) * NWARP;

        const float4 mv0 = m4[n0 * (E_ / 4) + lane];
        const float4 mv1 = m4[n1 * (E_ / 4) + lane];
        const float4 mv2 = m4[n2 * (E_ / 4) + lane];
        const float4 mv3 = m4[n3 * (E_ / 4) + lane];
        const float4 mv4 = m4[n4 * (E_ / 4) + lane];
        const float4 mv5 = m4[n5 * (E_ / 4) + lane];
        const float4 mv6 = m4[n6 * (E_ / 4) + lane];
        const float4 mv7 = m4[n7 * (E_ / 4) + lane];
        const float4 cv0 = c4[n0 * (E_ / 4) + lane];
        const float4 cv1 = c4[n1 * (E_ / 4) + lane];
        const float4 cv2 = c4[n2 * (E_ / 4) + lane];
        const float4 cv3 = c4[n3 * (E_ / 4) + lane];
        const float4 cv4 = c4[n4 * (E_ / 4) + lane];
        const float4 cv5 = c4[n5 * (E_ / 4) + lane];
        const float4 cv6 = c4[n6 * (E_ / 4) + lane];
        const float4 cv7 = c4[n7 * (E_ / 4) + lane];

        float sa0, so0, sa1, so1, sa2, so2, sa3, so3;
        float sa4, so4, sa5, so5, sa6, so6, sa7, so7;
        body(mv0, cv0, sa0, so0);
        body(mv1, cv1, sa1, so1);
        body(mv2, cv2, sa2, so2);
        body(mv3, cv3, sa3, so3);
        body(mv4, cv4, sa4, so4);
        body(mv5, cv5, sa5, so5);
        body(mv6, cv6, sa6, so6);
        body(mv7, cv7, sa7, so7);

        finish(n0, sa0, so0);
        finish(n1, sa1, so1);
        finish(n2, sa2, so2);
        finish(n3, sa3, so3);
        finish(n4, sa4, so4);
        finish(n5, sa5, so5);
        finish(n6, sa6, so6);
        finish(n7, sa7, so7);
    }
    // Tail rows j = 48, 49.
    {
        const int n0 = warp + 48 * NWARP;
        const int n1 = warp + 49 * NWARP;
        const float4 mv0 = m4[n0 * (E_ / 4) + lane];
        const float4 mv1 = m4[n1 * (E_ / 4) + lane];
        const float4 cv0 = c4[n0 * (E_ / 4) + lane];
        const float4 cv1 = c4[n1 * (E_ / 4) + lane];
        float sa0, so0, sa1, so1;
        body(mv0, cv0, sa0, so0);
        body(mv1, cv1, sa1, so1);
        finish(n0, sa0, so0);
        finish(n1, sa1, so1);
    }
    __syncthreads();

    // Block softmax over N_=200 with 128 threads: each thread covers
    // n = tid and n = tid + 128 (second only if < 200).
    const int  n2ok = (tid + NTHR) < N_;
    const float v1 = s_logit[tid];
    const float v2 = n2ok ? s_logit[tid + NTHR] : -CUDART_INF_F;

    float wm = fmaxf(v1, v2);
    #pragma unroll
    for (int o = 16; o; o >>= 1)
        wm = fmaxf(wm, __shfl_xor_sync(0xffffffffu, wm, o));
    if (lane == 0) s_red[warp] = wm;
    __syncthreads();

    float mx = fmaxf(fmaxf(s_red[0], s_red[1]), fmaxf(s_red[2], s_red[3]));

    const float ex1 = __expf(v1 - mx);
    const float ex2 = n2ok ? __expf(v2 - mx) : 0.f;

    float ws = ex1 + ex2;
    #pragma unroll
    for (int o = 16; o; o >>= 1)
        ws += __shfl_xor_sync(0xffffffffu, ws, o);
    __syncthreads();
    if (lane == 0) s_red[warp] = ws;
    __syncthreads();

    const float inv = 1.f / (s_red[0] + s_red[1] + s_red[2] + s_red[3]);

    out[(size_t)b * N_ + tid] = s_outd[tid] * ex1 * inv;
    if (n2ok)
        out[(size_t)b * N_ + tid + NTHR] = s_outd[tid + NTHR] * ex2 * inv;
}

extern "C" void kernel_launch(void* const* d_in, const int* in_sizes, int n_in,
                              void* d_out, int out_size)
{
    const float* q      = (const float*)d_in[0];
    const float* q_p    = (const float*)d_in[1];
    const float* m      = (const float*)d_in[2];
    const float* m_c    = (const float*)d_in[3];
    const float* A1     = (const float*)d_in[4];
    const float* A2     = (const float*)d_in[5];
    const float* biases = (const float*)d_in[6];
    const float* mask   = (const float*)d_in[7];
    float* out = (float*)d_out;

    const int B = in_sizes[0] / E_;   // 1024
    mass_kernel<<<B, NTHR>>>(q, q_p, m, m_c, A1, A2, biases, mask, out);
}

// round 7
// speedup vs baseline: 1.9931x; 1.0017x over previous
#include <cuda_runtime.h>
#include <cuda_bf16.h>
#include <math_constants.h>

// MASS_18897856102446: fused weighted-sq-dist attention
// out[b,n] = out_dist[b,n] * softmax_n(-(att_dist[b,n]*mask[b,n]))
// B=1024, N=200, E=128 (fp32). HBM-bound: m + m_c = ~210MB streamed once.
// R7: pair-merging tree reduction (31 SHFL for 16 warp-reductions instead of
//     80) to cut MIO traffic competing with LDG dispatch; bias/mask staged in
//     smem. Otherwise R6 structure: 128-thr CTAs, grid=1024 single wave,
//     8-row unroll, 16 float4 in flight, expanded-square 16-FFMA rows.

constexpr int N_ = 200;
constexpr int E_ = 128;
constexpr int NWARP = 4;
constexpr int NTHR = NWARP * 32;   // 128

__global__ __launch_bounds__(NTHR, 7)
void mass_kernel(const float* __restrict__ q,
                 const float* __restrict__ q_p,
                 const float* __restrict__ m,
                 const float* __restrict__ m_c,
                 const float* __restrict__ A1,
                 const float* __restrict__ A2,
                 const float* __restrict__ biases,
                 const float* __restrict__ mask,
                 float* __restrict__ out)
{
    const int b    = blockIdx.x;
    const int tid  = threadIdx.x;
    const int warp = tid >> 5;
    const int lane = tid & 31;

    __shared__ float4 s_v[E_ / 4], s_m2u[E_ / 4];
    __shared__ float  s_cq[NWARP];
    __shared__ float  s_logit[N_], s_outd[N_];
    __shared__ float  s_b2[N_], s_mk[N_];
    __shared__ float  s_red[NWARP];

    // Stage v = a1^2 + a2^2, m2u = -2*(a1^2 q + a2^2 qp); reduce Cq.
    {
        const float a1 = A1[tid];
        const float a2 = A2[tid];
        const float a1s = a1 * a1, a2s = a2 * a2;
        const float qv  = q  [(size_t)b * E_ + tid];
        const float qpv = q_p[(size_t)b * E_ + tid];
        reinterpret_cast<float*>(s_v)  [tid] = a1s + a2s;
        reinterpret_cast<float*>(s_m2u)[tid] = -2.f * (a1s * qv + a2s * qpv);

        // Stage 2*bias and mask once.
        s_b2[tid] = 2.f * biases[(size_t)b * N_ + tid];
        s_mk[tid] = mask  [(size_t)b * N_ + tid];
        if (tid + NTHR < N_) {
            s_b2[tid + NTHR] = 2.f * biases[(size_t)b * N_ + tid + NTHR];
            s_mk[tid + NTHR] = mask  [(size_t)b * N_ + tid + NTHR];
        }

        float c = a1s * qv * qv + a2s * qpv * qpv;
        #pragma unroll
        for (int o = 16; o; o >>= 1)
            c += __shfl_xor_sync(0xffffffffu, c, o);
        if (lane == 0) s_cq[warp] = c;
    }
    __syncthreads();

    const float4 vv = s_v[lane];
    const float4 mu = s_m2u[lane];
    const float  Cq = s_cq[0] + s_cq[1] + s_cq[2] + s_cq[3];

    const float4* __restrict__ m4 = reinterpret_cast<const float4*>(m   + (size_t)b * N_ * E_);
    const float4* __restrict__ c4 = reinterpret_cast<const float4*>(m_c + (size_t)b * N_ * E_);

    // sa = sum_e m*(v*m - 2u); so likewise with m_c. 16 FFMA per row.
    auto body = [&](const float4 mv, const float4 cv, float& sa, float& so) {
        float t;
        t = fmaf(vv.x, mv.x, mu.x); sa = mv.x * t;
        t = fmaf(vv.y, mv.y, mu.y); sa = fmaf(mv.y, t, sa);
        t = fmaf(vv.z, mv.z, mu.z); sa = fmaf(mv.z, t, sa);
        t = fmaf(vv.w, mv.w, mu.w); sa = fmaf(mv.w, t, sa);
        t = fmaf(vv.x, cv.x, mu.x); so = cv.x * t;
        t = fmaf(vv.y, cv.y, mu.y); so = fmaf(cv.y, t, so);
        t = fmaf(vv.z, cv.z, mu.z); so = fmaf(cv.z, t, so);
        t = fmaf(vv.w, cv.w, mu.w); so = fmaf(cv.w, t, so);
    };

    // Naive per-row finish (used for the 2 tail rows only).
    auto finish1 = [&](int n, float sa, float so) {
        #pragma unroll
        for (int o = 16; o; o >>= 1) {
            sa += __shfl_xor_sync(0xffffffffu, sa, o);
            so += __shfl_xor_sync(0xffffffffu, so, o);
        }
        if (lane == 0) {
            const float add = Cq + s_b2[n];
            const float mk  = s_mk[n];
            s_logit[n] = -((sa + add) * mk);
            s_outd[n]  = (so + add) * mk;
        }
    };

    const unsigned FULL = 0xffffffffu;
    const bool lo16 = (lane & 16) == 0;

    // 50 rows per warp (stride 4). 6 groups of 8 rows + 2 tail rows.
    #pragma unroll 1
    for (int k = 0; k < 48; k += 8) {
        const int nb = warp + k * NWARP;

        const float4 mv0 = m4[(nb + 0 * NWARP) * (E_ / 4) + lane];
        const float4 mv1 = m4[(nb + 1 * NWARP) * (E_ / 4) + lane];
        const float4 mv2 = m4[(nb + 2 * NWARP) * (E_ / 4) + lane];
        const float4 mv3 = m4[(nb + 3 * NWARP) * (E_ / 4) + lane];
        const float4 mv4 = m4[(nb + 4 * NWARP) * (E_ / 4) + lane];
        const float4 mv5 = m4[(nb + 5 * NWARP) * (E_ / 4) + lane];
        const float4 mv6 = m4[(nb + 6 * NWARP) * (E_ / 4) + lane];
        const float4 mv7 = m4[(nb + 7 * NWARP) * (E_ / 4) + lane];
        const float4 cv0 = c4[(nb + 0 * NWARP) * (E_ / 4) + lane];
        const float4 cv1 = c4[(nb + 1 * NWARP) * (E_ / 4) + lane];
        const float4 cv2 = c4[(nb + 2 * NWARP) * (E_ / 4) + lane];
        const float4 cv3 = c4[(nb + 3 * NWARP) * (E_ / 4) + lane];
        const float4 cv4 = c4[(nb + 4 * NWARP) * (E_ / 4) + lane];
        const float4 cv5 = c4[(nb + 5 * NWARP) * (E_ / 4) + lane];
        const float4 cv6 = c4[(nb + 6 * NWARP) * (E_ / 4) + lane];
        const float4 cv7 = c4[(nb + 7 * NWARP) * (E_ / 4) + lane];

        float sa0, so0, sa1, so1, sa2, so2, sa3, so3;
        float sa4, so4, sa5, so5, sa6, so6, sa7, so7;
        body(mv0, cv0, sa0, so0);
        body(mv1, cv1, sa1, so1);
        body(mv2, cv2, sa2, so2);
        body(mv3, cv3, sa3, so3);
        body(mv4, cv4, sa4, so4);
        body(mv5, cv5, sa5, so5);
        body(mv6, cv6, sa6, so6);
        body(mv7, cv7, sa7, so7);

        // ── pair-merging tree reduction: 16 values, 31 shuffles ──
        // L0 (offset 16): select sa (lanes<16) vs so (lanes>=16).
        float A, B;
        A = sa0 + __shfl_xor_sync(FULL, sa0, 16);
        B = so0 + __shfl_xor_sync(FULL, so0, 16);
        const float r0 = lo16 ? A : B;
        A = sa1 + __shfl_xor_sync(FULL, sa1, 16);
        B = so1 + __shfl_xor_sync(FULL, so1, 16);
        const float r1 = lo16 ? A : B;
        A = sa2 + __shfl_xor_sync(FULL, sa2, 16);
        B = so2 + __shfl_xor_sync(FULL, so2, 16);
        const float r2 = lo16 ? A : B;
        A = sa3 + __shfl_xor_sync(FULL, sa3, 16);
        B = so3 + __shfl_xor_sync(FULL, so3, 16);
        const float r3 = lo16 ? A : B;
        A = sa4 + __shfl_xor_sync(FULL, sa4, 16);
        B = so4 + __shfl_xor_sync(FULL, so4, 16);
        const float r4 = lo16 ? A : B;
        A = sa5 + __shfl_xor_sync(FULL, sa5, 16);
        B = so5 + __shfl_xor_sync(FULL, so5, 16);
        const float r5 = lo16 ? A : B;
        A = sa6 + __shfl_xor_sync(FULL, sa6, 16);
        B = so6 + __shfl_xor_sync(FULL, so6, 16);
        const float r6 = lo16 ? A : B;
        A = sa7 + __shfl_xor_sync(FULL, sa7, 16);
        B = so7 + __shfl_xor_sync(FULL, so7, 16);
        const float r7 = lo16 ? A : B;

        // L1 (offset 8): select row parity (bit3 of lane).
        const bool b3z = (lane & 8) == 0;
        A = r0 + __shfl_xor_sync(FULL, r0, 8);
        B = r1 + __shfl_xor_sync(FULL, r1, 8);
        const float s0 = b3z ? A : B;           // rows 0 / 1
        A = r2 + __shfl_xor_sync(FULL, r2, 8);
        B = r3 + __shfl_xor_sync(FULL, r3, 8);
        const float s1 = b3z ? A : B;           // rows 2 / 3
        A = r4 + __shfl_xor_sync(FULL, r4, 8);
        B = r5 + __shfl_xor_sync(FULL, r5, 8);
        const float s2 = b3z ? A : B;           // rows 4 / 5
        A = r6 + __shfl_xor_sync(FULL, r6, 8);
        B = r7 + __shfl_xor_sync(FULL, r7, 8);
        const float s3 = b3z ? A : B;           // rows 6 / 7

        // L2 (offset 4): bit2 selects row pair-group.
        const bool b2z = (lane & 4) == 0;
        A = s0 + __shfl_xor_sync(FULL, s0, 4);
        B = s1 + __shfl_xor_sync(FULL, s1, 4);
        const float t0 = b2z ? A : B;           // rows {0,1} / {2,3}
        A = s2 + __shfl_xor_sync(FULL, s2, 4);
        B = s3 + __shfl_xor_sync(FULL, s3, 4);
        const float t1 = b2z ? A : B;           // rows {4,5} / {6,7}

        // L3 (offset 2): bit1 selects half.
        const bool b1z = (lane & 2) == 0;
        A = t0 + __shfl_xor_sync(FULL, t0, 2);
        B = t1 + __shfl_xor_sync(FULL, t1, 2);
        const float u = b1z ? A : B;

        // L4 (offset 1): complete the reduction.
        const float f = u + __shfl_xor_sync(FULL, u, 1);

        // Writer lanes: even lanes; row = 4*bit1 + 2*bit2 + bit3; type = bit4.
        if ((lane & 1) == 0) {
            const int row = 4 * ((lane >> 1) & 1) + 2 * ((lane >> 2) & 1)
                          + ((lane >> 3) & 1);
            const int n   = nb + row * NWARP;
            const float val = (f + Cq + s_b2[n]) * s_mk[n];
            if (lo16) s_logit[n] = -val;
            else      s_outd[n]  =  val;
        }
    }
    // Tail rows j = 48, 49.
    {
        const int n0 = warp + 48 * NWARP;
        const int n1 = warp + 49 * NWARP;
        const float4 mv0 = m4[n0 * (E_ / 4) + lane];
        const float4 mv1 = m4[n1 * (E_ / 4) + lane];
        const float4 cv0 = c4[n0 * (E_ / 4) + lane];
        const float4 cv1 = c4[n1 * (E_ / 4) + lane];
        float sa0, so0, sa1, so1;
        body(mv0, cv0, sa0, so0);
        body(mv1, cv1, sa1, so1);
        finish1(n0, sa0, so0);
        finish1(n1, sa1, so1);
    }
    __syncthreads();

    // Block softmax over N_=200 with 128 threads.
    const int  n2ok = (tid + NTHR) < N_;
    const float v1 = s_logit[tid];
    const float v2 = n2ok ? s_logit[tid + NTHR] : -CUDART_INF_F;

    float wm = fmaxf(v1, v2);
    #pragma unroll
    for (int o = 16; o; o >>= 1)
        wm = fmaxf(wm, __shfl_xor_sync(0xffffffffu, wm, o));
    if (lane == 0) s_red[warp] = wm;
    __syncthreads();

    float mx = fmaxf(fmaxf(s_red[0], s_red[1]), fmaxf(s_red[2], s_red[3]));

    const float ex1 = __expf(v1 - mx);
    const float ex2 = n2ok ? __expf(v2 - mx) : 0.f;

    float ws = ex1 + ex2;
    #pragma unroll
    for (int o = 16; o; o >>= 1)
        ws += __shfl_xor_sync(0xffffffffu, ws, o);
    __syncthreads();
    if (lane == 0) s_red[warp] = ws;
    __syncthreads();

    const float inv = 1.f / (s_red[0] + s_red[1] + s_red[2] + s_red[3]);

    out[(size_t)b * N_ + tid] = s_outd[tid] * ex1 * inv;
    if (n2ok)
        out[(size_t)b * N_ + tid + NTHR] = s_outd[tid + NTHR] * ex2 * inv;
}

extern "C" void kernel_launch(void* const* d_in, const int* in_sizes, int n_in,
                              void* d_out, int out_size)
{
    const float* q      = (const float*)d_in[0];
    const float* q_p    = (const float*)d_in[1];
    const float* m      = (const float*)d_in[2];
    const float* m_c    = (const float*)d_in[3];
    const float* A1     = (const float*)d_in[4];
    const float* A2     = (const float*)d_in[5];
    const float* biases = (const float*)d_in[6];
    const float* mask   = (const float*)d_in[7];
    float* out = (float*)d_out;

    const int B = in_sizes[0] / E_;   // 1024
    mass_kernel<<<B, NTHR>>>(q, q_p, m, m_c, A1, A2, biases, mask, out);
}